// round 15
// baseline (speedup 1.0000x reference)
#include <cuda_runtime.h>
#include <math.h>

// ---------------------------------------------------------------------------
// StericClashConstraint: out = [pos (N*3 floats), loss]
// loss = 0.02 * mean_{NxN}( max(1 - dist_ij, 0) ), diagonal masked.
// R15: ONE kernel, ONE grid barrier, TRUE full occupancy.
//  R8's fused attempt died because __launch_bounds__(256,2) capped residency
//  at 512 thr/SM (occ 24%). Now: 296 blocks x 1024 thr, launch_bounds(1024,2)
//  -> 2048 thr/SM, exactly one wave (296 = 148*2) -> spin barrier safe.
//  - phase 0 (no loops): pos->out copy (tid<3n) + bin (tid<n).
//  - grid barrier (the only one).
//  - phase 1: 28n k-split pair units over 303K threads = exactly TWO
//    manually-unrolled units/thread -> two independent load chains (ILP x2
//    without halving thread count, cf. R11 lesson).
//  - tail: zero OTHER parity counts (tid<NCELLS; race-free, no 2nd barrier),
//    block reduce, 296-ticket finalize, parity flip.
//  - Symmetry halving (13 positive neighbors + home with idx>, x2 weight).
// Cell grid 32^3 over [-16,16): boundary clamp exact (cell >= 1, d2-tested).
// ---------------------------------------------------------------------------

#define GRID_DIM 32
#define NCELLS   (GRID_DIM * GRID_DIM * GRID_DIM)   // 32768
#define CAP      32
#define ORIGIN   (-16.0f)
#define CWEIGHT  0.02
#define NPTS     16384
#define NB       296
#define TPB      1024
#define NTH      (NB * TPB)                          // 303104

__device__ int      g_count[2][NCELLS];              // static zero-init
__device__ float4   g_cellslot[NCELLS * CAP];
__device__ double   g_sum;
__device__ unsigned int g_done;
__device__ int      g_parity = 0;

__device__ unsigned int g_bar_count = 0;
__device__ volatile unsigned int g_bar_gen = 0;      // monotone across replays

__device__ __forceinline__ int clampi(int v, int lo, int hi) {
    return v < lo ? lo : (v > hi ? hi : v);
}

__device__ __forceinline__ void grid_barrier() {
    __syncthreads();
    if (threadIdx.x == 0) {
        unsigned int gen = g_bar_gen;
        __threadfence();
        if (atomicAdd(&g_bar_count, 1u) == NB - 1) {
            g_bar_count = 0;
            __threadfence();
            g_bar_gen = gen + 1;
        } else {
            while (g_bar_gen == gen) __nanosleep(32);
        }
        __threadfence();
    }
    __syncthreads();
}

__global__ void __launch_bounds__(TPB, 2)
fused_kernel(const float* __restrict__ pos, float* __restrict__ out, int n) {
    const int tid = blockIdx.x * TPB + threadIdx.x;
    const int par = g_parity;
    const int* __restrict__ cnts = g_count[par];

    // ---- phase 0: pos passthrough + bin (no loops) ----
    if (tid < 3 * n) out[tid] = pos[tid];
    if (tid < n) {
        float x = pos[3 * tid + 0];
        float y = pos[3 * tid + 1];
        float z = pos[3 * tid + 2];
        int cx = clampi((int)floorf(x - ORIGIN), 0, GRID_DIM - 1);
        int cy = clampi((int)floorf(y - ORIGIN), 0, GRID_DIM - 1);
        int cz = clampi((int)floorf(z - ORIGIN), 0, GRID_DIM - 1);
        int cc = (cz * GRID_DIM + cy) * GRID_DIM + cx;
        int slot = atomicAdd(&g_count[par][cc], 1);
        if (slot < CAP)
            g_cellslot[cc * CAP + slot] =
                make_float4(x, y, z, __int_as_float(tid));
    }

    grid_barrier();

    // ---- phase 1: two k-split pair units per thread, unrolled for ILP ----
    // unit u -> item (u>>1), slot parity (u&1); item = i*14 + c.
    // c in [0,9): dz=+1,dy=c/3-1,dx=c%3-1; c in [9,12): dz=0,dy=+1,dx=c-10;
    // c==12: dz=0,dy=0,dx=+1; c==13: home cell (idx(q) > idx(p) only).
    const int U = 28 * n;                       // 458752 units
    float lsum = 0.0f;

    #define DO_UNIT(u)                                                      \
    {                                                                       \
        const int item = (u) >> 1;                                          \
        const int half = (u) & 1;                                           \
        const int i    = item / 14;                                         \
        const int c    = item - i * 14;                                     \
        float px = pos[3 * i + 0];                                          \
        float py = pos[3 * i + 1];                                          \
        float pz = pos[3 * i + 2];                                          \
        int cx = clampi((int)floorf(px - ORIGIN), 0, GRID_DIM - 1);         \
        int cy = clampi((int)floorf(py - ORIGIN), 0, GRID_DIM - 1);         \
        int cz = clampi((int)floorf(pz - ORIGIN), 0, GRID_DIM - 1);         \
        bool homecell = (c == 13);                                          \
        int dx8, dy8, dz8;                                                  \
        if (c < 9)       { dz8 = 1; dy8 = c / 3 - 1; dx8 = c % 3 - 1; }     \
        else if (c < 12) { dz8 = 0; dy8 = 1;         dx8 = c - 10;    }     \
        else             { dz8 = 0; dy8 = 0;         dx8 = 1;         }     \
        int gx = cx + (homecell ? 0 : dx8);                                 \
        int gy = cy + (homecell ? 0 : dy8);                                 \
        int gz = cz + (homecell ? 0 : dz8);                                 \
        bool valid = (unsigned)gx < GRID_DIM && (unsigned)gy < GRID_DIM &&  \
                     (unsigned)gz < GRID_DIM;                               \
        if (valid) {                                                        \
            int cell = (gz * GRID_DIM + gy) * GRID_DIM + gx;                \
            int cnt = cnts[cell];                                           \
            const float4* cp = &g_cellslot[cell * CAP];                     \
            float4 q0 = cp[half];                                           \
            float4 q1 = cp[half + 2];                                       \
            cnt = cnt < CAP ? cnt : CAP;                                    \
            {                                                               \
                float ddx = px - q0.x, ddy = py - q0.y, ddz = pz - q0.z;    \
                float d2 = fmaf(ddx, ddx, fmaf(ddy, ddy, ddz * ddz));       \
                bool ok = half < cnt && d2 < 1.0f &&                        \
                          (!homecell || __float_as_int(q0.w) > i);          \
                if (ok) lsum += 1.0f - sqrtf(d2);                           \
            }                                                               \
            {                                                               \
                float ddx = px - q1.x, ddy = py - q1.y, ddz = pz - q1.z;    \
                float d2 = fmaf(ddx, ddx, fmaf(ddy, ddy, ddz * ddz));       \
                bool ok = half + 2 < cnt && d2 < 1.0f &&                    \
                          (!homecell || __float_as_int(q1.w) > i);          \
                if (ok) lsum += 1.0f - sqrtf(d2);                           \
            }                                                               \
            for (int k = half + 4; k < cnt; k += 2) {                       \
                float4 q = cp[k];                                           \
                float ddx = px - q.x, ddy = py - q.y, ddz = pz - q.z;       \
                float d2 = fmaf(ddx, ddx, fmaf(ddy, ddy, ddz * ddz));       \
                bool ok = d2 < 1.0f &&                                      \
                          (!homecell || __float_as_int(q.w) > i);           \
                if (ok) lsum += 1.0f - sqrtf(d2);                           \
            }                                                               \
        }                                                                   \
    }

    if (tid < U) DO_UNIT(tid)
    {
        int u2 = tid + NTH;
        if (u2 < U) DO_UNIT(u2)
    }
    #undef DO_UNIT

    // ---- tail: zero the OTHER parity's counts (unread -> race-free) ----
    if (tid < NCELLS) g_count[1 - par][tid] = 0;

    // ---- reduce: warp -> block -> double atomic -> ticket -> write ----
    __shared__ float s_warp[TPB / 32];
    #pragma unroll
    for (int off = 16; off > 0; off >>= 1)
        lsum += __shfl_down_sync(0xFFFFFFFFu, lsum, off);
    int lane = threadIdx.x & 31;
    int wid  = threadIdx.x >> 5;
    if (lane == 0) s_warp[wid] = lsum;
    __syncthreads();
    if (wid == 0) {
        float v = (lane < TPB / 32) ? s_warp[lane] : 0.0f;
        #pragma unroll
        for (int off = 16; off > 0; off >>= 1)
            v += __shfl_down_sync(0xFFFFFFFFu, v, off);
        if (lane == 0) {
            if (v != 0.0f) atomicAdd(&g_sum, (double)v);
            __threadfence();
            unsigned int prev = atomicAdd(&g_done, 1u);
            if (prev == NB - 1) {
                double nn = (double)n * (double)n;
                out[3 * n] = (float)(g_sum * (2.0 * CWEIGHT / nn));
                g_sum    = 0.0;
                g_done   = 0u;
                g_parity = 1 - par;
            }
        }
    }
}

extern "C" void kernel_launch(void* const* d_in, const int* in_sizes, int n_in,
                              void* d_out, int out_size) {
    const float* pos = (const float*)d_in[0];
    float* out = (float*)d_out;
    int n = in_sizes[0] / 3;   // 16384
    fused_kernel<<<NB, TPB>>>(pos, out, n);
}